// round 12
// baseline (speedup 1.0000x reference)
#include <cuda_runtime.h>
#include <cuda_fp16.h>
#include <stdint.h>

// ---------------------------------------------------------------------------
// EdgeNetwork: messages_e = sum_h H[e,h]*(hw_e @ W2[h]^T) + (hw_e @ b2-tile)
// Single fused kernel (R11 WIN + per-g immediate scaling):
// 148 CTAs x 128 edges, 8 warps m32n64; step = 4 sub-blocks of (32 HMMA into
// dg[4][4], then fp32 H-scale into acc) so FFMA overlaps next block's HMMA
// and register pressure drops (was 247, spill-prone). Leftover 1056 edges
// folded in as 132 (16e x 64c) chunks on warps 0-3 of CTAs 0..131.
// ---------------------------------------------------------------------------

#define DD        128
#define EDIM      16
#define EH        128
#define NSTEPS    129
#define STEP_BYTES 32768
#define SLOTS     3

// ---- smem layout ----
#define MB_FULL(i)  ((i)*8)
#define MB_EMPTY(i) (32 + (i)*8)
#define HW_OFF      1024                 // 144 x 256B = 36864 -> ends 37888
#define HT_OFF      37888                // 129*128*4 = 66048 -> ends 103936
#define HTX_OFF     103936               // 129*16*4 = 8256 -> ends 112192
#define W2_OFF      112640               // 3 x 32768 -> ends 210944
#define SMEM_TOTAL  210944
// prologue scratch (inside HW region, dead before hw image build)
#define SCR_EF      1024
#define SCR_W1      9216
#define SCR_B1      17408
#define SCR_EFX     17920

static __device__ __align__(128) unsigned char g_w2h[(size_t)NSTEPS * STEP_BYTES];

__device__ __forceinline__ uint32_t s2u(const void* p) {
    return (uint32_t)__cvta_generic_to_shared(p);
}
__device__ __forceinline__ uint32_t swz_chunk(uint32_t c, uint32_t r7) {
    return (c & 8u) | ((c & 7u) ^ r7);
}
__device__ __forceinline__ void mbar_init(uint32_t a, uint32_t cnt) {
    asm volatile("mbarrier.init.shared.b64 [%0], %1;" :: "r"(a), "r"(cnt) : "memory");
}
__device__ __forceinline__ void mbar_expect_tx(uint32_t a, uint32_t bytes) {
    asm volatile("mbarrier.arrive.expect_tx.shared.b64 _, [%0], %1;"
                 :: "r"(a), "r"(bytes) : "memory");
}
__device__ __forceinline__ void mbar_arrive(uint32_t a) {
    asm volatile("mbarrier.arrive.shared.b64 _, [%0];" :: "r"(a) : "memory");
}
__device__ __forceinline__ void mbar_wait(uint32_t a, uint32_t parity) {
    asm volatile(
        "{\n\t.reg .pred P;\n\t"
        "W_%=:\n\t"
        "mbarrier.try_wait.parity.shared.b64 P, [%0], %1;\n\t"
        "@P bra.uni D_%=;\n\t"
        "bra.uni W_%=;\n\t"
        "D_%=:\n\t}"
        :: "r"(a), "r"(parity) : "memory");
}
__device__ __forceinline__ void bulk_g2s(uint32_t dst, const void* src, uint32_t bytes,
                                         uint32_t mbar) {
    asm volatile(
        "cp.async.bulk.shared::cluster.global.mbarrier::complete_tx::bytes [%0], [%1], %2, [%3];"
        :: "r"(dst), "l"(src), "r"(bytes), "r"(mbar) : "memory");
}
__device__ __forceinline__ void ldsm_x4(uint32_t& r0, uint32_t& r1, uint32_t& r2, uint32_t& r3,
                                        uint32_t addr) {
    asm volatile("ldmatrix.sync.aligned.m8n8.x4.shared.b16 {%0,%1,%2,%3}, [%4];"
                 : "=r"(r0), "=r"(r1), "=r"(r2), "=r"(r3) : "r"(addr));
}
__device__ __forceinline__ void mma_acc(float* c, const uint32_t* a,
                                        uint32_t b0, uint32_t b1) {
    asm volatile(
        "mma.sync.aligned.m16n8k16.row.col.f32.f16.f16.f32 "
        "{%0,%1,%2,%3}, {%4,%5,%6,%7}, {%8,%9}, {%0,%1,%2,%3};"
        : "+f"(c[0]), "+f"(c[1]), "+f"(c[2]), "+f"(c[3])
        : "r"(a[0]), "r"(a[1]), "r"(a[2]), "r"(a[3]), "r"(b0), "r"(b1));
}
__device__ __forceinline__ void mma_zc(float* d, const uint32_t* a,
                                       uint32_t b0, uint32_t b1) {
    asm volatile(
        "mma.sync.aligned.m16n8k16.row.col.f32.f16.f16.f32 "
        "{%0,%1,%2,%3}, {%4,%5,%6,%7}, {%8,%9}, {%10,%11,%12,%13};"
        : "=f"(d[0]), "=f"(d[1]), "=f"(d[2]), "=f"(d[3])
        : "r"(a[0]), "r"(a[1]), "r"(a[2]), "r"(a[3]), "r"(b0), "r"(b1),
          "f"(0.f), "f"(0.f), "f"(0.f), "f"(0.f));
}

// ---------------------------------------------------------------------------
__global__ void __launch_bounds__(128) w2_prepass(const float* __restrict__ W2,
                                                  const float* __restrict__ b2) {
    const int h = blockIdx.x;
    const int q = blockIdx.y;
    const int tid = threadIdx.x;
    const float* src = (h < EH) ? (W2 + (size_t)h * (DD * DD)) : b2;
    unsigned char* dst = g_w2h + (size_t)h * STEP_BYTES;
    #pragma unroll
    for (int it = 0; it < 4; ++it) {
        int cid = q * 512 + it * 128 + tid;
        int i = cid >> 4;
        int c = cid & 15;
        const float* s = src + (size_t)i * DD + c * 8;
        float4 a = *(const float4*)s;
        float4 b = *(const float4*)(s + 4);
        __half2 h0 = __floats2half2_rn(a.x, a.y);
        __half2 h1 = __floats2half2_rn(a.z, a.w);
        __half2 h2 = __floats2half2_rn(b.x, b.y);
        __half2 h3 = __floats2half2_rn(b.z, b.w);
        uint32_t off = (uint32_t)i * 256u + (swz_chunk((uint32_t)c, (uint32_t)(i & 7)) << 4);
        uint4 v;
        v.x = *(uint32_t*)&h0; v.y = *(uint32_t*)&h1;
        v.z = *(uint32_t*)&h2; v.w = *(uint32_t*)&h3;
        *(uint4*)(dst + off) = v;
    }
}

// ---------------------------------------------------------------------------
// Fused main: 128 edges/CTA + optional 16x64 extra chunk.
// ---------------------------------------------------------------------------
__global__ void __launch_bounds__(256, 1)
edge_main(const float* __restrict__ hw, const float* __restrict__ ef,
          const float* __restrict__ W1, const float* __restrict__ b1,
          float* __restrict__ out, int n, int exbase, int nchunks) {
    extern __shared__ __align__(1024) unsigned char smem[];
    const uint32_t smem_b = s2u(smem);
    const int tid = threadIdx.x;
    const int lane = tid & 31;
    const int wid = tid >> 5;
    const int warp_m = wid & 3;
    const int warp_n = wid >> 2;
    const int e0 = blockIdx.x * 128;

    const int cid = blockIdx.x;
    const bool ctaChunk = (cid < nchunks);
    const int xgrp = cid >> 1;
    const int xcolh = cid & 1;
    const int eX0 = exbase + xgrp * 16;
    const bool warpChunk = ctaChunk && (wid < 4);

    if (tid == 0) {
        #pragma unroll
        for (int i = 0; i < SLOTS; ++i) {
            mbar_init(smem_b + MB_FULL(i), 1);
            mbar_init(smem_b + MB_EMPTY(i), 8);
        }
        asm volatile("fence.mbarrier_init.release.cluster;" ::: "memory");
    }
    __syncthreads();
    if (tid == 0) {
        #pragma unroll
        for (int i = 0; i < SLOTS; ++i) {
            mbar_expect_tx(smem_b + MB_FULL(i), STEP_BYTES);
            bulk_g2s(smem_b + W2_OFF + i * STEP_BYTES, g_w2h + (size_t)i * STEP_BYTES,
                     STEP_BYTES, smem_b + MB_FULL(i));
        }
    }

    // -------- stage ef / W1 / b1 / ef_x --------
    {
        float* ef_s = (float*)(smem + SCR_EF);
        float* w1_s = (float*)(smem + SCR_W1);
        float* b1_s = (float*)(smem + SCR_B1);
        float* efx_s = (float*)(smem + SCR_EFX);
        ((float4*)ef_s)[tid] = ((const float4*)(ef + (size_t)e0 * EDIM))[tid];
        ((float4*)ef_s)[tid + 256] = ((const float4*)(ef + (size_t)e0 * EDIM))[tid + 256];
        ((float4*)w1_s)[tid] = ((const float4*)W1)[tid];
        ((float4*)w1_s)[tid + 256] = ((const float4*)W1)[tid + 256];
        if (tid < EH) b1_s[tid] = b1[tid];
        if (tid < 64) {
            int e = tid >> 2;
            float4 v = make_float4(0.f, 0.f, 0.f, 0.f);
            if (ctaChunk && eX0 + e < n)
                v = *(const float4*)(ef + (size_t)(eX0 + e) * EDIM + (tid & 3) * 4);
            ((float4*)efx_s)[tid] = v;
        }
    }
    __syncthreads();

    // -------- MLP: Ht[h][e] fp32 (main 128 edges), step 128 = 1.0 --------
    {
        const float* ef_s = (const float*)(smem + SCR_EF);
        const float* w1_s = (const float*)(smem + SCR_W1);
        const float* b1_s = (const float*)(smem + SCR_B1);
        float* ht = (float*)(smem + HT_OFF);
        const int e = tid >> 1;
        const int part = tid & 1;
        float efr[EDIM];
        #pragma unroll
        for (int k = 0; k < EDIM; ++k) efr[k] = ef_s[e * EDIM + k];
        const int h0 = part * 64;
        #pragma unroll 4
        for (int hh = 0; hh < 64; hh += 4) {
            float4 acc4 = *(const float4*)(b1_s + h0 + hh);
            #pragma unroll
            for (int k = 0; k < EDIM; ++k) {
                float4 w = *(const float4*)(w1_s + k * EH + h0 + hh);
                acc4.x += efr[k] * w.x; acc4.y += efr[k] * w.y;
                acc4.z += efr[k] * w.z; acc4.w += efr[k] * w.w;
            }
            ht[(h0 + hh + 0) * 128 + e] = fmaxf(acc4.x, 0.f);
            ht[(h0 + hh + 1) * 128 + e] = fmaxf(acc4.y, 0.f);
            ht[(h0 + hh + 2) * 128 + e] = fmaxf(acc4.z, 0.f);
            ht[(h0 + hh + 3) * 128 + e] = fmaxf(acc4.w, 0.f);
        }
        if (part == 0) ht[128 * 128 + e] = 1.0f;
    }

    // -------- MLP for extra 16 edges --------
    if (ctaChunk) {
        const float* efx_s = (const float*)(smem + SCR_EFX);
        const float* w1_s = (const float*)(smem + SCR_W1);
        const float* b1_s = (const float*)(smem + SCR_B1);
        float* htx = (float*)(smem + HTX_OFF);
        const int e = tid >> 4;
        const int part = tid & 15;
        float efr[EDIM];
        #pragma unroll
        for (int k = 0; k < EDIM; ++k) efr[k] = efx_s[e * EDIM + k];
        const int h0 = part * 8;
        #pragma unroll
        for (int hh = 0; hh < 8; hh += 4) {
            float4 acc4 = *(const float4*)(b1_s + h0 + hh);
            #pragma unroll
            for (int k = 0; k < EDIM; ++k) {
                float4 w = *(const float4*)(w1_s + k * EH + h0 + hh);
                acc4.x += efr[k] * w.x; acc4.y += efr[k] * w.y;
                acc4.z += efr[k] * w.z; acc4.w += efr[k] * w.w;
            }
            htx[(h0 + hh + 0) * 16 + e] = fmaxf(acc4.x, 0.f);
            htx[(h0 + hh + 1) * 16 + e] = fmaxf(acc4.y, 0.f);
            htx[(h0 + hh + 2) * 16 + e] = fmaxf(acc4.z, 0.f);
            htx[(h0 + hh + 3) * 16 + e] = fmaxf(acc4.w, 0.f);
        }
        if (part == 0) htx[128 * 16 + e] = 1.0f;
    }
    __syncthreads();

    // -------- hw fp16 image (rows 0..127 main, 128..143 extra) --------
    {
        #pragma unroll
        for (int q = 0; q < 8; ++q) {
            int cid2 = tid + q * 256;
            int r = cid2 >> 4;
            int c = cid2 & 15;
            const float* s = hw + (size_t)(e0 + r) * DD + c * 8;
            float4 a = *(const float4*)s;
            float4 b = *(const float4*)(s + 4);
            __half2 h0 = __floats2half2_rn(a.x, a.y);
            __half2 h1 = __floats2half2_rn(a.z, a.w);
            __half2 h2 = __floats2half2_rn(b.x, b.y);
            __half2 h3 = __floats2half2_rn(b.z, b.w);
            uint32_t off = (uint32_t)r * 256u + (swz_chunk((uint32_t)c, (uint32_t)(r & 7)) << 4);
            uint4 v;
            v.x = *(uint32_t*)&h0; v.y = *(uint32_t*)&h1;
            v.z = *(uint32_t*)&h2; v.w = *(uint32_t*)&h3;
            *(uint4*)(smem + HW_OFF + off) = v;
        }
        if (ctaChunk) {
            int r = tid >> 4;
            int c = tid & 15;
            float4 a = make_float4(0.f, 0.f, 0.f, 0.f), b = a;
            if (eX0 + r < n) {
                const float* s = hw + (size_t)(eX0 + r) * DD + c * 8;
                a = *(const float4*)s;
                b = *(const float4*)(s + 4);
            }
            __half2 h0 = __floats2half2_rn(a.x, a.y);
            __half2 h1 = __floats2half2_rn(a.z, a.w);
            __half2 h2 = __floats2half2_rn(b.x, b.y);
            __half2 h3 = __floats2half2_rn(b.z, b.w);
            int rr = 128 + r;
            uint32_t off = (uint32_t)rr * 256u + (swz_chunk((uint32_t)c, (uint32_t)(rr & 7)) << 4);
            uint4 v;
            v.x = *(uint32_t*)&h0; v.y = *(uint32_t*)&h1;
            v.z = *(uint32_t*)&h2; v.w = *(uint32_t*)&h3;
            *(uint4*)(smem + HW_OFF + off) = v;
        }
    }
    __syncthreads();

    // -------- A fragments into registers (step-invariant) --------
    const uint32_t rx = (uint32_t)(lane & 7);
    const uint32_t lhi = (uint32_t)(lane >> 4);
    uint32_t coffv[8];
    #pragma unroll
    for (int kt = 0; kt < 8; ++kt)
        coffv[kt] = swz_chunk((uint32_t)(kt * 2) + lhi, rx) << 4;

    uint32_t A0[8][4], A1[8][4];
    {
        const uint32_t aBase0 = smem_b + HW_OFF + (uint32_t)(warp_m * 32 + (lane & 15)) * 256u;
        const uint32_t aBase1 = aBase0 + 16u * 256u;
        #pragma unroll
        for (int kt = 0; kt < 8; ++kt) {
            ldsm_x4(A0[kt][0], A0[kt][1], A0[kt][2], A0[kt][3], aBase0 + coffv[kt]);
            ldsm_x4(A1[kt][0], A1[kt][1], A1[kt][2], A1[kt][3], aBase1 + coffv[kt]);
        }
    }

    uint32_t bR[4];
    #pragma unroll
    for (int g = 0; g < 4; ++g)
        bR[g] = (uint32_t)(warp_n * 64 + g * 16 + (lane & 15)) * 256u;

    const uint32_t aBaseX = smem_b + HW_OFF + (uint32_t)(128 + (lane & 15)) * 256u;
    const uint32_t bRX = (uint32_t)(xcolh * 64 + wid * 16 + (lane & 15)) * 256u;

    const float* ht = (const float*)(smem + HT_OFF);
    const float* htx = (const float*)(smem + HTX_OFF);
    const int quad = lane >> 2;
    const int hrow = warp_m * 32 + quad;

    float acc[2][8][4];
    #pragma unroll
    for (int mf = 0; mf < 2; ++mf)
        #pragma unroll
        for (int f = 0; f < 8; ++f)
            #pragma unroll
            for (int q = 0; q < 4; ++q) acc[mf][f][q] = 0.f;
    float accx[2][4];
    #pragma unroll
    for (int f = 0; f < 2; ++f)
        #pragma unroll
        for (int q = 0; q < 4; ++q) accx[f][q] = 0.f;

    // -------- main loop --------
    int slot = 0, use = 0;
    for (int s = 0; s < NSTEPS; ++s) {
        const uint32_t par = (uint32_t)use & 1u;
        mbar_wait(smem_b + MB_FULL(slot), par);

        const float hA0 = ht[s * 128 + hrow];
        const float hB0 = ht[s * 128 + hrow + 8];
        const float hA1 = ht[s * 128 + hrow + 16];
        const float hB1 = ht[s * 128 + hrow + 24];
        const uint32_t bSlot = smem_b + W2_OFF + slot * STEP_BYTES;

        // 4 sub-blocks: 32 HMMA into dg[4][4], then immediate fp32 scale.
        #pragma unroll
        for (int g = 0; g < 4; ++g) {
            float dg[4][4];   // [mf0b0, mf0b1, mf1b0, mf1b1]
            const uint32_t bAddr = bSlot + bR[g];
            #pragma unroll
            for (int kt = 0; kt < 8; ++kt) {
                uint32_t b0, b1r, b2, b3;
                ldsm_x4(b0, b1r, b2, b3, bAddr + coffv[kt]);
                if (kt == 0) {
                    mma_zc(dg[0], A0[0], b0, b2);
                    mma_zc(dg[1], A0[0], b1r, b3);
                    mma_zc(dg[2], A1[0], b0, b2);
                    mma_zc(dg[3], A1[0], b1r, b3);
                } else {
                    mma_acc(dg[0], A0[kt], b0, b2);
                    mma_acc(dg[1], A0[kt], b1r, b3);
                    mma_acc(dg[2], A1[kt], b0, b2);
                    mma_acc(dg[3], A1[kt], b1r, b3);
                }
            }
            #pragma unroll
            for (int b = 0; b < 2; ++b) {
                float* a0 = acc[0][g * 2 + b];
                float* a1 = acc[1][g * 2 + b];
                a0[0] += hA0 * dg[b][0];      a0[1] += hA0 * dg[b][1];
                a0[2] += hB0 * dg[b][2];      a0[3] += hB0 * dg[b][3];
                a1[0] += hA1 * dg[2 + b][0];  a1[1] += hA1 * dg[2 + b][1];
                a1[2] += hB1 * dg[2 + b][2];  a1[3] += hB1 * dg[2 + b][3];
            }
        }

        if (!warpChunk) {
            __syncwarp();
            if (lane == 0) mbar_arrive(smem_b + MB_EMPTY(slot));
        }

        // extra chunk (warps 0-3 of chunk-carrying CTAs)
        if (warpChunk) {
            const float hXA = htx[s * 16 + quad];
            const float hXB = htx[s * 16 + quad + 8];
            float dx[2][4];
            #pragma unroll
            for (int kt = 0; kt < 8; ++kt) {
                uint32_t ax0, ax1, ax2, ax3, b0, b1r, b2, b3;
                ldsm_x4(ax0, ax1, ax2, ax3, aBaseX + coffv[kt]);
                ldsm_x4(b0, b1r, b2, b3, bSlot + bRX + coffv[kt]);
                uint32_t ax[4] = {ax0, ax1, ax2, ax3};
                if (kt == 0) {
                    mma_zc(dx[0], ax, b0, b2);
                    mma_zc(dx[1], ax, b1r, b3);
                } else {
                    mma_acc(dx[0], ax, b0, b2);
                    mma_acc(dx[1], ax, b1r, b3);
                }
            }
            __syncwarp();
            if (lane == 0) mbar_arrive(smem_b + MB_EMPTY(slot));
            #pragma unroll
            for (int f = 0; f < 2; ++f) {
                accx[f][0] += hXA * dx[f][0];  accx[f][1] += hXA * dx[f][1];
                accx[f][2] += hXB * dx[f][2];  accx[f][3] += hXB * dx[f][3];
            }
        }

        if (tid == 0 && s + SLOTS < NSTEPS) {
            mbar_wait(smem_b + MB_EMPTY(slot), par);
            mbar_expect_tx(smem_b + MB_FULL(slot), STEP_BYTES);
            bulk_g2s(smem_b + W2_OFF + slot * STEP_BYTES,
                     g_w2h + (size_t)(s + SLOTS) * STEP_BYTES, STEP_BYTES,
                     smem_b + MB_FULL(slot));
        }
        if (++slot == SLOTS) { slot = 0; ++use; }
    }

    // -------- epilogue: main tile --------
    #pragma unroll
    for (int mf = 0; mf < 2; ++mf) {
        const int er = e0 + warp_m * 32 + mf * 16 + quad;
        #pragma unroll
        for (int gg = 0; gg < 4; ++gg)
            #pragma unroll
            for (int b = 0; b < 2; ++b) {
                const int f = gg * 2 + b;
                const int col = warp_n * 64 + gg * 16 + b * 8 + (lane & 3) * 2;
                *(float2*)(out + (size_t)er * DD + col) =
                    make_float2(acc[mf][f][0], acc[mf][f][1]);
                *(float2*)(out + (size_t)(er + 8) * DD + col) =
                    make_float2(acc[mf][f][2], acc[mf][f][3]);
            }
    }
    // -------- epilogue: extra chunk --------
    if (warpChunk) {
        const int er = eX0 + quad;
        #pragma unroll
        for (int b = 0; b < 2; ++b) {
            const int col = xcolh * 64 + wid * 16 + b * 8 + (lane & 3) * 2;
            if (er < n)
                *(float2*)(out + (size_t)er * DD + col) =
                    make_float2(accx[b][0], accx[b][1]);
            if (er + 8 < n)
                *(float2*)(out + (size_t)(er + 8) * DD + col) =
                    make_float2(accx[b][2], accx[b][3]);
        }
    }
}

// ---------------------------------------------------------------------------
extern "C" void kernel_launch(void* const* d_in, const int* in_sizes, int n_in,
                              void* d_out, int out_size) {
    const float* hw = (const float*)d_in[1];
    const float* ef = (const float*)d_in[2];
    const float* W1 = (const float*)d_in[3];
    const float* b1 = (const float*)d_in[4];
    const float* W2 = (const float*)d_in[5];
    const float* b2 = (const float*)d_in[6];
    const int n = in_sizes[1] / DD;

    w2_prepass<<<dim3(NSTEPS, 4), 128>>>(W2, b2);

    int full = n / 128;
    if (full > 148) full = 148;
    const int exbase = full * 128;
    const int rem = n - exbase;
    const int nchunks = ((rem + 15) / 16) * 2;

    if (full > 0) {
        cudaFuncSetAttribute(edge_main, cudaFuncAttributeMaxDynamicSharedMemorySize,
                             SMEM_TOTAL);
        edge_main<<<full, 256, SMEM_TOTAL>>>(hw, ef, W1, b1, (float*)d_out, n,
                                             exbase, nchunks);
    }
}